// round 13
// baseline (speedup 1.0000x reference)
#include <cuda_runtime.h>

#define HIDDEN 32
#define FF 40
#define TSTEPS 512
#define BATCH 16384
#define EPB 128           /* elements per block; each thread handles 4 */
#define THREADS 320       /* 10 warps x 4 column-pairs each = 40 pairs = 80 cols */

typedef unsigned long long u64;

__device__ __forceinline__ u64 pk(float a, float b) {
    u64 r; asm("mov.b64 %0,{%1,%2};" : "=l"(r) : "f"(a), "f"(b)); return r;
}
__device__ __forceinline__ void upk(u64 v, float& a, float& b) {
    asm("mov.b64 {%0,%1},%2;" : "=f"(a), "=f"(b) : "l"(v));
}
__device__ __forceinline__ u64 f2fma(u64 a, u64 b, u64 c) {
    u64 d; asm("fma.rn.f32x2 %0,%1,%2,%3;" : "=l"(d) : "l"(a), "l"(b), "l"(c)); return d;
}
// sigmoid via ex2/rcp approx (~1e-6 rel; proven across rounds)
__device__ __forceinline__ float sigm(float x) {
    float e, r;
    asm("ex2.approx.ftz.f32 %0,%1;" : "=f"(e) : "f"(x * -1.4426950408889634f));
    asm("rcp.approx.ftz.f32 %0,%1;" : "=f"(r) : "f"(1.0f + e));
    return r;
}

// Dynamic smem layout (bytes; all bases 16B-aligned)
#define OFF_WF   0            /* fused Wf[40][80] f32 = 12800              */
#define OFF_U    12800        /* u-row [80] f32                            */
#define OFF_BF   13120        /* fused recurrent bias [80]                 */
#define OFF_B0   13440        /* plain layer-1 bias (t=0) [80]             */
#define OFF_W2HO 13760        /* W2ho [40] -> 13920                        */
#define OFF_SBUF 13920        /* u64[2][20*EPB] = 40960 -> 54880           */
#define OFF_OBUF 54880        /* f32[2][5*EPB]  = 5120  -> 60000           */
#define SMEM_TOTAL 60000

__global__ void __launch_bounds__(THREADS, 1) rnn_f128_kernel(
    const float* __restrict__ inp,
    const float* __restrict__ W1hh, const float* __restrict__ b1hh,
    const float* __restrict__ W2hh, const float* __restrict__ b2hh,
    const float* __restrict__ W1ho, const float* __restrict__ b1ho,
    const float* __restrict__ W2ho, const float* __restrict__ b2ho,
    float* __restrict__ out)
{
    extern __shared__ __align__(16) char smem[];
    float* sWf   = (float*)(smem + OFF_WF);    // [k<40][j<80]; j<40 hh, j>=40 ho
    float* sU    = (float*)(smem + OFF_U);
    float* sBf   = (float*)(smem + OFF_BF);
    float* sB0   = (float*)(smem + OFF_B0);
    float* sW2ho = (float*)(smem + OFF_W2HO);
    u64*   sbuf  = (u64*)  (smem + OFF_SBUF);  // s = sigmoid(z_hh), 20 pairs, x2 parity
    float* obuf  = (float*)(smem + OFF_OBUF);  // 5 output partials, x2 parity

    const int tid = threadIdx.x;

    // ---- init: Wf[k][j] = sum_i W2hh[k][i] * W1x[i][jcol] (fused) ----
    for (int idx = tid; idx < 40 * 80; idx += THREADS) {
        int k = idx / 80, j = idx % 80;
        const float* W1p = (j < 40) ? (W1hh + j) : (W1ho + (j - 40));  // stride FF over i
        const float* W2p = W2hh + k * HIDDEN;
        float acc = 0.0f;
        #pragma unroll
        for (int i = 0; i < HIDDEN; i++) acc += W2p[i] * W1p[i * FF];
        sWf[idx] = acc;
    }
    for (int j = tid; j < 80; j += THREADS) {
        const float* W1p = (j < 40) ? (W1hh + j) : (W1ho + (j - 40));
        float b1 = (j < 40) ? b1hh[j] : b1ho[j - 40];
        float acc = 0.0f;
        #pragma unroll
        for (int i = 0; i < HIDDEN; i++) acc += b2hh[i] * W1p[i * FF];
        sB0[j] = b1;              // t=0: h0 = 0 -> plain layer-1 bias
        sBf[j] = b1 + acc;        // t>0: bias absorbs b2hh @ W1[0:32]
        sU[j]  = W1p[32 * FF];    // input-row weights W1[32][jcol]
    }
    for (int j = tid; j < FF; j += THREADS) sW2ho[j] = W2ho[j];
    const float bias_o = b2ho[0];
    __syncthreads();

    const int lane = tid & 31;
    const int cg   = tid >> 5;          // warp = column slice: j-pairs [4cg, 4cg+4)
    const bool is_hh = (cg < 5);        // cols 0..39 -> s state; 40..79 -> output head
    const bool is_comb = (cg == 0);

    const size_t ebase = (size_t)blockIdx.x * EPB;
    const float* __restrict__ ip[4];
    float* __restrict__ op[4];
    #pragma unroll
    for (int k = 0; k < 4; k++) {
        ip[k] = inp + (ebase + lane + 32 * k) * TSTEPS;
        op[k] = out + (ebase + lane + 32 * k) * TSTEPS;
    }

    // Hoist loop-invariant 4-pair vectors into registers (zero per-step LDS).
    u64 Ureg[4], Bfreg[4], Woreg[4];
    {
        const u64* Up  = (const u64*)sU  + 4 * cg;
        const u64* Bfp = (const u64*)sBf + 4 * cg;
        int wb = is_hh ? 0 : 4 * (cg - 5);
        const u64* Wop = (const u64*)sW2ho + wb;
        #pragma unroll
        for (int q = 0; q < 4; q++) { Ureg[q] = Up[q]; Bfreg[q] = Bfp[q]; Woreg[q] = Wop[q]; }
    }

    // ---- t = 0: z = u0 * Urow + B0 (h0 = 0 exactly) ----
    u64 z[4][4];
    {
        const u64* B0p = (const u64*)sB0 + 4 * cg;
        #pragma unroll
        for (int q = 0; q < 4; q++) {
            u64 Bq = B0p[q];
            #pragma unroll
            for (int k = 0; k < 4; k++) {
                float u0 = ip[k][0];
                z[k][q] = f2fma(pk(u0, u0), Ureg[q], Bq);
            }
        }
    }

    #pragma unroll 1
    for (int t = 0; t < TSTEPS; t++) {
        const int par = t & 1;
        float un[4];
        #pragma unroll
        for (int k = 0; k < 4; k++) un[k] = ip[k][(t + 1) & (TSTEPS - 1)];

        // ===== phase 1: consume z[t] =====
        if (is_hh) {
            // s = sigmoid(z_hh) -> sbuf[par], pairs [4cg, 4cg+4)
            u64* sb = sbuf + par * (20 * EPB);
            #pragma unroll
            for (int q = 0; q < 4; q++) {
                #pragma unroll
                for (int k = 0; k < 4; k++) {
                    float a, b; upk(z[k][q], a, b);
                    sb[(4 * cg + q) * EPB + lane + 32 * k] = pk(sigm(a), sigm(b));
                }
            }
        } else {
            // partial output dot: sigmoid(z_ho) . W2ho[slice] -> obuf[par][cg-5]
            u64 acc[4] = {0ull, 0ull, 0ull, 0ull};
            #pragma unroll
            for (int q = 0; q < 4; q++) {
                #pragma unroll
                for (int k = 0; k < 4; k++) {
                    float a, b; upk(z[k][q], a, b);
                    acc[k] = f2fma(pk(sigm(a), sigm(b)), Woreg[q], acc[k]);
                }
            }
            float* ob = obuf + par * (5 * EPB) + (cg - 5) * EPB;
            #pragma unroll
            for (int k = 0; k < 4; k++) {
                float a, b; upk(acc[k], a, b);
                ob[lane + 32 * k] = a + b;
            }
        }

        __syncthreads();   // s + output partials published

        // combiner warp writes out[t] (uses h_{t-1}: matches reference)
        if (is_comb) {
            const float* ob = obuf + par * (5 * EPB);
            #pragma unroll
            for (int k = 0; k < 4; k++) {
                int ei = lane + 32 * k;
                op[k][t] = ob[ei] + ob[EPB + ei] + ob[2 * EPB + ei]
                         + ob[3 * EPB + ei] + ob[4 * EPB + ei] + bias_o;
            }
        }

        // ===== phase 2: GEMV -> z[t+1] = s @ Wf + u_{t+1}*U + Bf =====
        #pragma unroll
        for (int q = 0; q < 4; q++) {
            u64 Bq = Bfreg[q];
            #pragma unroll
            for (int k = 0; k < 4; k++) z[k][q] = f2fma(pk(un[k], un[k]), Ureg[q], Bq);
        }
        {
            const u64* sb = sbuf + par * (20 * EPB);
            #pragma unroll 2
            for (int kp = 0; kp < 20; kp++) {
                u64 p0[4], p1[4];
                #pragma unroll
                for (int k = 0; k < 4; k++) {
                    float s0, s1; upk(sb[kp * EPB + lane + 32 * k], s0, s1);
                    p0[k] = pk(s0, s0); p1[k] = pk(s1, s1);
                }
                // row 2kp: 2 aligned LDS.128 cover this warp's 4 pairs
                const ulonglong2* w0 = (const ulonglong2*)(sWf + (2 * kp) * 80) + 2 * cg;
                ulonglong2 Wa = w0[0], Wb = w0[1];
                #pragma unroll
                for (int k = 0; k < 4; k++) {
                    z[k][0] = f2fma(p0[k], Wa.x, z[k][0]);
                    z[k][1] = f2fma(p0[k], Wa.y, z[k][1]);
                    z[k][2] = f2fma(p0[k], Wb.x, z[k][2]);
                    z[k][3] = f2fma(p0[k], Wb.y, z[k][3]);
                }
                // row 2kp+1
                const ulonglong2* w1 = (const ulonglong2*)(sWf + (2 * kp + 1) * 80) + 2 * cg;
                ulonglong2 Wc = w1[0], Wd = w1[1];
                #pragma unroll
                for (int k = 0; k < 4; k++) {
                    z[k][0] = f2fma(p1[k], Wc.x, z[k][0]);
                    z[k][1] = f2fma(p1[k], Wc.y, z[k][1]);
                    z[k][2] = f2fma(p1[k], Wd.x, z[k][2]);
                    z[k][3] = f2fma(p1[k], Wd.y, z[k][3]);
                }
            }
        }
        // single barrier per step: next iteration writes the OTHER parity of
        // sbuf/obuf; barrier-ordering guarantees no reader/writer overlap.
    }
}

extern "C" void kernel_launch(void* const* d_in, const int* in_sizes, int n_in,
                              void* d_out, int out_size) {
    const float* inp  = (const float*)d_in[0];
    const float* W1hh = (const float*)d_in[1];
    const float* b1hh = (const float*)d_in[2];
    const float* W2hh = (const float*)d_in[3];
    const float* b2hh = (const float*)d_in[4];
    const float* W1ho = (const float*)d_in[5];
    const float* b1ho = (const float*)d_in[6];
    const float* W2ho = (const float*)d_in[7];
    const float* b2ho = (const float*)d_in[8];
    float* out = (float*)d_out;

    // Idempotent, capture-safe.
    cudaFuncSetAttribute(rnn_f128_kernel,
                         cudaFuncAttributeMaxDynamicSharedMemorySize, SMEM_TOTAL);

    dim3 grid(BATCH / EPB);   // 128 blocks x 320 threads: 10 warps/SM, 2.5/SMSP
    dim3 block(THREADS);
    rnn_f128_kernel<<<grid, block, SMEM_TOTAL>>>(inp, W1hh, b1hh, W2hh, b2hh,
                                                 W1ho, b1ho, W2ho, b2ho, out);
}

// round 14
// speedup vs baseline: 1.1215x; 1.1215x over previous
#include <cuda_runtime.h>

#define HIDDEN 32
#define FF 40
#define TSTEPS 512
#define BATCH 16384
#define EPB 128           /* elements per block; each thread handles 4 */
#define THREADS 256       /* 8 warps: 4 hh (recurrence) + 4 ho (output head) */
#define CH 4              /* steps per chunk */
#define NCH (TSTEPS/CH)   /* 128 chunks */

typedef unsigned long long u64;

__device__ __forceinline__ u64 pk(float a, float b) {
    u64 r; asm("mov.b64 %0,{%1,%2};" : "=l"(r) : "f"(a), "f"(b)); return r;
}
__device__ __forceinline__ void upk(u64 v, float& a, float& b) {
    asm("mov.b64 {%0,%1},%2;" : "=f"(a), "=f"(b) : "l"(v));
}
__device__ __forceinline__ u64 f2fma(u64 a, u64 b, u64 c) {
    u64 d; asm("fma.rn.f32x2 %0,%1,%2,%3;" : "=l"(d) : "l"(a), "l"(b), "l"(c)); return d;
}
// sigmoid via ex2/rcp approx (~1e-6 rel; proven across rounds)
__device__ __forceinline__ float sigm(float x) {
    float e, r;
    asm("ex2.approx.ftz.f32 %0,%1;" : "=f"(e) : "f"(x * -1.4426950408889634f));
    asm("rcp.approx.ftz.f32 %0,%1;" : "=f"(r) : "f"(1.0f + e));
    return r;
}

// Dynamic smem layout (bytes; every u64 region 8B-aligned)
#define OFF_WF   0                    /* fused Wf[40][80] f32 = 12800 */
#define OFF_U    12800                /* u-row [80]                   */
#define OFF_BF   13120                /* fused recurrent bias [80]    */
#define OFF_B0   13440                /* plain t=0 bias [80]          */
#define OFF_W2HO 13760                /* W2ho [40] -> 13920           */
#define OFF_SBUF 13920                /* u64[2][CH][20*EPB] = 163840  */
#define OFF_OBUF (13920 + 163840)     /* f32[CH][4][EPB] = 8192       */
#define SMEM_TOTAL (OFF_OBUF + 8192)  /* 185952 bytes                 */
#define SLOTSTEP (20 * EPB)           /* u64 per step slot            */
#define SLOTBUF  (CH * SLOTSTEP)      /* u64 per chunk buffer         */

__global__ void __launch_bounds__(THREADS, 1) rnn_pipe_kernel(
    const float* __restrict__ inp,
    const float* __restrict__ W1hh, const float* __restrict__ b1hh,
    const float* __restrict__ W2hh, const float* __restrict__ b2hh,
    const float* __restrict__ W1ho, const float* __restrict__ b1ho,
    const float* __restrict__ W2ho, const float* __restrict__ b2ho,
    float* __restrict__ out)
{
    extern __shared__ __align__(16) char smem[];
    float* sWf   = (float*)(smem + OFF_WF);    // [k<40][j<80]; j<40 hh, j>=40 ho
    float* sU    = (float*)(smem + OFF_U);
    float* sBf   = (float*)(smem + OFF_BF);
    float* sB0   = (float*)(smem + OFF_B0);
    float* sW2ho = (float*)(smem + OFF_W2HO);
    u64*   sbuf  = (u64*)  (smem + OFF_SBUF);  // s ring: 2 chunk buffers x CH slots
    float* obuf  = (float*)(smem + OFF_OBUF);  // [step m][slice][elem]

    const int tid = threadIdx.x;

    // ---- init: Wf[k][j] = sum_i W2hh[k][i] * W1x[i][jcol] (fused) ----
    for (int idx = tid; idx < 40 * 80; idx += THREADS) {
        int k = idx / 80, j = idx % 80;
        const float* W1p = (j < 40) ? (W1hh + j) : (W1ho + (j - 40));  // stride FF over i
        const float* W2p = W2hh + k * HIDDEN;
        float acc = 0.0f;
        #pragma unroll
        for (int i = 0; i < HIDDEN; i++) acc += W2p[i] * W1p[i * FF];
        sWf[idx] = acc;
    }
    for (int j = tid; j < 80; j += THREADS) {
        const float* W1p = (j < 40) ? (W1hh + j) : (W1ho + (j - 40));
        float b1 = (j < 40) ? b1hh[j] : b1ho[j - 40];
        float acc = 0.0f;
        #pragma unroll
        for (int i = 0; i < HIDDEN; i++) acc += b2hh[i] * W1p[i * FF];
        sB0[j] = b1;              // t=0: h0 = 0 -> plain layer-1 bias
        sBf[j] = b1 + acc;        // t>0: bias absorbs b2hh @ W1[0:32]
        sU[j]  = W1p[32 * FF];
    }
    for (int j = tid; j < FF; j += THREADS) sW2ho[j] = W2ho[j];
    const float bias_o = b2ho[0];
    __syncthreads();

    const int lane = tid & 31;
    const int wid  = tid >> 5;            // 0..7
    const bool is_hh = (wid < 4);         // warps 0-3: recurrence; 4-7: output head
    const int cg   = wid & 3;             // column slice within role
    const int JB   = 5 * cg + (is_hh ? 0 : 20);   // pair base into 80-col arrays

    const size_t ebase = (size_t)blockIdx.x * EPB;
    const float* __restrict__ ip[4];
    float* __restrict__ op[4];
    #pragma unroll
    for (int k = 0; k < 4; k++) {
        ip[k] = inp + (ebase + lane + 32 * k) * TSTEPS;
        op[k] = out + (ebase + lane + 32 * k) * TSTEPS;
    }

    // Hoist loop-invariant 5-pair vectors into registers.
    u64 Ureg[5], Bfreg[5], B0reg[5], Woreg[5];
    {
        const u64* Up  = (const u64*)sU  + JB;
        const u64* Bfp = (const u64*)sBf + JB;
        const u64* B0p = (const u64*)sB0 + JB;
        const u64* Wop = (const u64*)sW2ho + 5 * cg;   // meaningful for ho warps
        #pragma unroll
        for (int q = 0; q < 5; q++) {
            Ureg[q] = Up[q]; Bfreg[q] = Bfp[q]; B0reg[q] = B0p[q]; Woreg[q] = Wop[q];
        }
    }

    #pragma unroll 1
    for (int c = 0; c <= NCH; c++) {
        if (is_hh) {
            if (c < NCH) {
                // ===== produce s chunk c into sbuf[c&1] =====
                u64* sbw = sbuf + (c & 1) * SLOTBUF;
                const u64* sbprev3 = sbuf + ((c + 1) & 1) * SLOTBUF + (CH - 1) * SLOTSTEP;
                float uu[CH][4];
                #pragma unroll
                for (int m = 0; m < CH; m++)
                    #pragma unroll
                    for (int k = 0; k < 4; k++) uu[m][k] = ip[k][CH * c + m];

                #pragma unroll 1
                for (int m = 0; m < CH; m++) {
                    const int t = CH * c + m;
                    u64 z[4][5];
                    if (t == 0) {
                        #pragma unroll
                        for (int q = 0; q < 5; q++)
                            #pragma unroll
                            for (int k = 0; k < 4; k++)
                                z[k][q] = f2fma(pk(uu[m][k], uu[m][k]), Ureg[q], B0reg[q]);
                    } else {
                        #pragma unroll
                        for (int q = 0; q < 5; q++)
                            #pragma unroll
                            for (int k = 0; k < 4; k++)
                                z[k][q] = f2fma(pk(uu[m][k], uu[m][k]), Ureg[q], Bfreg[q]);
                        const u64* sp = (m == 0) ? sbprev3 : (sbw + (m - 1) * SLOTSTEP);
                        #pragma unroll 2
                        for (int kp = 0; kp < 20; kp++) {
                            u64 p0[4], p1[4];
                            #pragma unroll
                            for (int k = 0; k < 4; k++) {
                                float s0, s1; upk(sp[kp * EPB + lane + 32 * k], s0, s1);
                                p0[k] = pk(s0, s0); p1[k] = pk(s1, s1);
                            }
                            const u64* w0 = (const u64*)(sWf + (2 * kp) * 80) + JB;
                            #pragma unroll
                            for (int q = 0; q < 5; q++) {
                                u64 W = w0[q];
                                #pragma unroll
                                for (int k = 0; k < 4; k++) z[k][q] = f2fma(p0[k], W, z[k][q]);
                            }
                            const u64* w1 = (const u64*)(sWf + (2 * kp + 1) * 80) + JB;
                            #pragma unroll
                            for (int q = 0; q < 5; q++) {
                                u64 W = w1[q];
                                #pragma unroll
                                for (int k = 0; k < 4; k++) z[k][q] = f2fma(p1[k], W, z[k][q]);
                            }
                        }
                    }
                    // s_t = sigmoid(z) -> slot m, pairs [5cg, 5cg+5)
                    u64* dst = sbw + m * SLOTSTEP;
                    #pragma unroll
                    for (int q = 0; q < 5; q++)
                        #pragma unroll
                        for (int k = 0; k < 4; k++) {
                            float a, b; upk(z[k][q], a, b);
                            dst[(5 * cg + q) * EPB + lane + 32 * k] = pk(sigm(a), sigm(b));
                        }
                    // hh-only barrier: s_t fully published before next step reads it
                    asm volatile("bar.sync 1, 128;" ::: "memory");
                }
            }
        } else {
            if (c == 0) {
                // ===== out[0]: z_ho = u0*U + B0 (h0 = 0), no s needed =====
                u64 z[4][5];
                #pragma unroll
                for (int q = 0; q < 5; q++)
                    #pragma unroll
                    for (int k = 0; k < 4; k++) {
                        float u0 = ip[k][0];
                        z[k][q] = f2fma(pk(u0, u0), Ureg[q], B0reg[q]);
                    }
                u64 acc[4] = {0ull, 0ull, 0ull, 0ull};
                #pragma unroll
                for (int q = 0; q < 5; q++)
                    #pragma unroll
                    for (int k = 0; k < 4; k++) {
                        float a, b; upk(z[k][q], a, b);
                        acc[k] = f2fma(pk(sigm(a), sigm(b)), Woreg[q], acc[k]);
                    }
                #pragma unroll
                for (int k = 0; k < 4; k++) {
                    float a, b; upk(acc[k], a, b);
                    obuf[(0 * 4 + cg) * EPB + lane + 32 * k] = a + b;
                }
                asm volatile("bar.sync 2, 128;" ::: "memory");
                if (cg == 0) {
                    #pragma unroll
                    for (int k = 0; k < 4; k++) {
                        int ei = lane + 32 * k;
                        op[k][0] = obuf[ei] + obuf[EPB + ei] + obuf[2 * EPB + ei]
                                 + obuf[3 * EPB + ei] + bias_o;
                    }
                }
            } else {
                // ===== consume s chunk c-1 from sbuf[(c-1)&1] =====
                const u64* sbr = sbuf + ((c - 1) & 1) * SLOTBUF;
                #pragma unroll 1
                for (int m = 0; m < CH; m++) {
                    const int tout = CH * (c - 1) + 1 + m;   // uses s_{tout-1} = slot m
                    if (tout < TSTEPS) {
                        u64 z[4][5];
                        #pragma unroll
                        for (int q = 0; q < 5; q++)
                            #pragma unroll
                            for (int k = 0; k < 4; k++) {
                                float ut = ip[k][tout];
                                z[k][q] = f2fma(pk(ut, ut), Ureg[q], Bfreg[q]);
                            }
                        const u64* sp = sbr + m * SLOTSTEP;
                        #pragma unroll 2
                        for (int kp = 0; kp < 20; kp++) {
                            u64 p0[4], p1[4];
                            #pragma unroll
                            for (int k = 0; k < 4; k++) {
                                float s0, s1; upk(sp[kp * EPB + lane + 32 * k], s0, s1);
                                p0[k] = pk(s0, s0); p1[k] = pk(s1, s1);
                            }
                            const u64* w0 = (const u64*)(sWf + (2 * kp) * 80) + JB;
                            #pragma unroll
                            for (int q = 0; q < 5; q++) {
                                u64 W = w0[q];
                                #pragma unroll
                                for (int k = 0; k < 4; k++) z[k][q] = f2fma(p0[k], W, z[k][q]);
                            }
                            const u64* w1 = (const u64*)(sWf + (2 * kp + 1) * 80) + JB;
                            #pragma unroll
                            for (int q = 0; q < 5; q++) {
                                u64 W = w1[q];
                                #pragma unroll
                                for (int k = 0; k < 4; k++) z[k][q] = f2fma(p1[k], W, z[k][q]);
                            }
                        }
                        u64 acc[4] = {0ull, 0ull, 0ull, 0ull};
                        #pragma unroll
                        for (int q = 0; q < 5; q++)
                            #pragma unroll
                            for (int k = 0; k < 4; k++) {
                                float a, b; upk(z[k][q], a, b);
                                acc[k] = f2fma(pk(sigm(a), sigm(b)), Woreg[q], acc[k]);
                            }
                        #pragma unroll
                        for (int k = 0; k < 4; k++) {
                            float a, b; upk(acc[k], a, b);
                            obuf[(m * 4 + cg) * EPB + lane + 32 * k] = a + b;
                        }
                    }
                }
                asm volatile("bar.sync 2, 128;" ::: "memory");
                {   // combiner: ho warp cg writes out for step m = cg
                    const int tout = CH * (c - 1) + 1 + cg;
                    if (tout < TSTEPS) {
                        const float* ob = obuf + (cg * 4) * EPB;
                        #pragma unroll
                        for (int k = 0; k < 4; k++) {
                            int ei = lane + 32 * k;
                            op[k][tout] = ob[ei] + ob[EPB + ei] + ob[2 * EPB + ei]
                                        + ob[3 * EPB + ei] + bias_o;
                        }
                    }
                }
            }
        }
        __syncthreads();   // chunk boundary: swap ring buffers (all 256 threads)
    }
}

extern "C" void kernel_launch(void* const* d_in, const int* in_sizes, int n_in,
                              void* d_out, int out_size) {
    const float* inp  = (const float*)d_in[0];
    const float* W1hh = (const float*)d_in[1];
    const float* b1hh = (const float*)d_in[2];
    const float* W2hh = (const float*)d_in[3];
    const float* b2hh = (const float*)d_in[4];
    const float* W1ho = (const float*)d_in[5];
    const float* b1ho = (const float*)d_in[6];
    const float* W2ho = (const float*)d_in[7];
    const float* b2ho = (const float*)d_in[8];
    float* out = (float*)d_out;

    // Idempotent, capture-safe.
    cudaFuncSetAttribute(rnn_pipe_kernel,
                         cudaFuncAttributeMaxDynamicSharedMemorySize, SMEM_TOTAL);

    dim3 grid(BATCH / EPB);   // 128 blocks x 256 threads
    dim3 block(THREADS);
    rnn_pipe_kernel<<<grid, block, SMEM_TOTAL>>>(inp, W1hh, b1hh, W2hh, b2hh,
                                                 W1ho, b1ho, W2ho, b2ho, out);
}

// round 16
// speedup vs baseline: 2.5860x; 2.3058x over previous
#include <cuda_runtime.h>
#include <cuda_bf16.h>
#include <cstdint>

#define HIDDEN 32
#define FF 40
#define TSTEPS 512
#define BATCH 16384
#define THREADS 256        /* 8 warps x 16 rows = 128 elements per block */
#define EPB 128

typedef unsigned long long u64;
typedef unsigned int u32;

// sigmoid via ex2/rcp approx (proven rel_err ~2e-7 across all passing rounds)
__device__ __forceinline__ float sigm(float x) {
    float e, r;
    asm("ex2.approx.ftz.f32 %0,%1;" : "=f"(e) : "f"(x * -1.4426950408889634f));
    asm("rcp.approx.ftz.f32 %0,%1;" : "=f"(r) : "f"(1.0f + e));
    return r;
}
__device__ __forceinline__ u32 bfbits(float x) {       // rn bf16, low 16 bits
    return (u32)__bfloat16_as_ushort(__float2bfloat16(x));
}
__device__ __forceinline__ float bf2f(u32 b) { return __uint_as_float(b << 16); }

// one m16n8k16 bf16 mma, accumulate in place
__device__ __forceinline__ void mma16816(float* d, u32 a0, u32 a1, u32 a2, u32 a3,
                                         u32 b0, u32 b1) {
    asm volatile(
        "mma.sync.aligned.m16n8k16.row.col.f32.bf16.bf16.f32 "
        "{%0,%1,%2,%3}, {%4,%5,%6,%7}, {%8,%9}, {%0,%1,%2,%3};"
        : "+f"(d[0]), "+f"(d[1]), "+f"(d[2]), "+f"(d[3])
        : "r"(a0), "r"(a1), "r"(a2), "r"(a3), "r"(b0), "r"(b1));
}

// weight value (bf16 bits) at fused-K position k, column n
__device__ u32 wv16(int k, int n, const float* sWf, const float* sBf, const float* sUa) {
    float v; bool lo = false;
    if      (k <  40)  v = sWf[k * 80 + n];                 // s_hi * W_hi
    else if (k <  80){ v = sWf[(k - 40) * 80 + n]; lo = 1; }// s_hi * W_lo
    else if (k < 120)  v = sWf[(k - 80) * 80 + n];          // s_lo * W_hi
    else if (k == 120) v = sBf[n];                          // 1 * Bf_hi
    else if (k == 121){ v = sBf[n]; lo = 1; }               // 1 * Bf_lo
    else if (k == 122) v = sUa[n];                          // u_hi * U_hi
    else if (k == 123){ v = sUa[n]; lo = 1; }               // u_hi * U_lo
    else if (k == 124) v = sUa[n];                          // u_lo * U_hi
    else return 0u;
    u32 hb = bfbits(v);
    if (!lo) return hb;
    return bfbits(v - bf2f(hb));
}

__global__ void __launch_bounds__(THREADS, 1) rnn_mma_kernel(
    const float* __restrict__ inp,
    const float* __restrict__ W1hh, const float* __restrict__ b1hh,
    const float* __restrict__ W2hh, const float* __restrict__ b2hh,
    const float* __restrict__ W1ho, const float* __restrict__ b1ho,
    const float* __restrict__ W2ho, const float* __restrict__ b2ho,
    float* __restrict__ out)
{
    __shared__ float sWf[40 * 80];     // fused Wf[kk][n]
    __shared__ u64   sBfrag[80 * 32];  // pre-packed B fragments [q*10+j][lane]
    __shared__ float sU[80], sB0[80], sBf[80], sW2ho[FF];

    const int tid = threadIdx.x;

    // ---- init: fused Wf[kk][n] = sum_i W2hh[kk][i] * W1x[i][col] ----
    for (int idx = tid; idx < 40 * 80; idx += THREADS) {
        int kk = idx / 80, n = idx % 80;
        const float* W1p = (n < FF) ? (W1hh + n) : (W1ho + (n - FF));
        const float* W2p = W2hh + kk * HIDDEN;
        float acc = 0.0f;
        #pragma unroll
        for (int i = 0; i < HIDDEN; i++) acc += W2p[i] * W1p[i * FF];
        sWf[idx] = acc;
    }
    for (int n = tid; n < 80; n += THREADS) {
        const float* W1p = (n < FF) ? (W1hh + n) : (W1ho + (n - FF));
        float b1 = (n < FF) ? b1hh[n] : b1ho[n - FF];
        float acc = 0.0f;
        #pragma unroll
        for (int i = 0; i < HIDDEN; i++) acc += b2hh[i] * W1p[i * FF];
        sB0[n] = b1;                 // t=0 bias (h0 = 0 exactly)
        sBf[n] = b1 + acc;           // recurrent bias (absorbs b2hh @ W1[0:32])
        sU[n]  = W1p[32 * FF];       // input-row weights
    }
    for (int n = tid; n < FF; n += THREADS) sW2ho[n] = W2ho[n];
    const float bias_o = b2ho[0];
    __syncthreads();

    // ---- pack B fragments: tile (q,j), per lane: b0=(k0,k0+1), b1=(k0+8,k0+9), n=8j+g ----
    for (int idx = tid; idx < 80 * 32; idx += THREADS) {
        int tile = idx >> 5, ln = idx & 31;
        int q = tile / 10, j = tile % 10;
        int n = 8 * j + (ln >> 2);
        int k0 = 16 * q + (ln & 3) * 2;
        u32 b0 = wv16(k0, n, sWf, sBf, sU) | (wv16(k0 + 1, n, sWf, sBf, sU) << 16);
        u32 b1 = wv16(k0 + 8, n, sWf, sBf, sU) | (wv16(k0 + 9, n, sWf, sBf, sU) << 16);
        sBfrag[idx] = (u64)b0 | ((u64)b1 << 32);
    }
    __syncthreads();

    const int lane = tid & 31;
    const int w    = tid >> 5;
    const int tig  = lane & 3;        // thread-in-group (column selector)
    const int grp  = lane >> 2;       // row group
    const int e0   = blockIdx.x * EPB + w * 16 + grp;   // rows grp, grp+8 of warp tile
    const int e1   = e0 + 8;
    const float* __restrict__ ip0 = inp + (size_t)e0 * TSTEPS;
    const float* __restrict__ ip1 = inp + (size_t)e1 * TSTEPS;
    float* __restrict__ op0 = out + (size_t)e0 * TSTEPS;
    float* __restrict__ op1 = out + (size_t)e1 * TSTEPS;

    // hoist W2ho slices for the 5 ho tiles (cols 40..79)
    float wo0[5], wo1[5];
    #pragma unroll
    for (int jj = 0; jj < 5; jj++) {
        wo0[jj] = sW2ho[8 * jj + tig * 2];
        wo1[jj] = sW2ho[8 * jj + tig * 2 + 1];
    }

    // ---- t=0: z = u0*U + B0 (exact fp32; h0 = 0) ----
    float z[10][4];
    {
        float u00 = ip0[0], u01 = ip1[0];
        #pragma unroll
        for (int j = 0; j < 10; j++) {
            int c = 8 * j + tig * 2;
            float Uc = sU[c], Uc1 = sU[c + 1], Bc = sB0[c], Bc1 = sB0[c + 1];
            z[j][0] = fmaf(u00, Uc, Bc);  z[j][1] = fmaf(u00, Uc1, Bc1);
            z[j][2] = fmaf(u01, Uc, Bc);  z[j][3] = fmaf(u01, Uc1, Bc1);
        }
    }

    float un0 = ip0[1], un1 = ip1[1];

    #pragma unroll 1
    for (int t = 0; t < TSTEPS; t++) {
        // ===== output head from z_t (ho tiles 5..9), quad-reduce, write =====
        {
            float a0 = 0.0f, a1 = 0.0f;
            #pragma unroll
            for (int jj = 0; jj < 5; jj++) {
                int j = jj + 5;
                a0 = fmaf(sigm(z[j][0]), wo0[jj], a0);
                a0 = fmaf(sigm(z[j][1]), wo1[jj], a0);
                a1 = fmaf(sigm(z[j][2]), wo0[jj], a1);
                a1 = fmaf(sigm(z[j][3]), wo1[jj], a1);
            }
            a0 += __shfl_xor_sync(0xffffffffu, a0, 1);
            a0 += __shfl_xor_sync(0xffffffffu, a0, 2);
            a1 += __shfl_xor_sync(0xffffffffu, a1, 1);
            a1 += __shfl_xor_sync(0xffffffffu, a1, 2);
            if (tig == 0) { op0[t] = a0 + bias_o; op1[t] = a1 + bias_o; }
        }

        if (t == TSTEPS - 1) break;

        // ===== s = sigmoid(z_hh): rn-split bf16 hi/lo pairs (register-local) =====
        u32 ph[5][2], pl[5][2];    // [tile][row-half]: packed (col, col+1)
        #pragma unroll
        for (int j = 0; j < 5; j++) {
            #pragma unroll
            for (int r = 0; r < 2; r++) {
                float sa = sigm(z[j][2 * r]);
                float sb = sigm(z[j][2 * r + 1]);
                u32 ha = bfbits(sa), hb = bfbits(sb);
                ph[j][r] = ha | (hb << 16);
                u32 la = bfbits(sa - bf2f(ha)), lb = bfbits(sb - bf2f(hb));
                pl[j][r] = la | (lb << 16);
            }
        }
        // bias/u columns (k 120..127): per-tig constants
        u32 q7r0, q7r1;
        {
            u32 uh0 = bfbits(un0), uh1 = bfbits(un1);
            u32 ul0 = bfbits(un0 - bf2f(uh0)), ul1 = bfbits(un1 - bf2f(uh1));
            q7r0 = (tig == 0) ? 0x3F803F80u
                 : (tig == 1) ? (uh0 | (uh0 << 16))
                 : (tig == 2) ? ul0 : 0u;
            q7r1 = (tig == 0) ? 0x3F803F80u
                 : (tig == 1) ? (uh1 | (uh1 << 16))
                 : (tig == 2) ? ul1 : 0u;
        }
        // prefetch next input
        int tn = (t + 2 < TSTEPS) ? (t + 2) : (TSTEPS - 1);
        un0 = ip0[tn]; un1 = ip1[tn];

        // A slices q=0..7 (D-fragment of z IS next A-fragment: register-local)
        u32 A[8][4];
        #pragma unroll
        for (int q = 0; q < 2; q++) {          // k0..31: s_hi tiles 0..3
            A[q][0] = ph[2*q][0]; A[q][1] = ph[2*q][1];
            A[q][2] = ph[2*q+1][0]; A[q][3] = ph[2*q+1][1];
        }
        A[2][0] = ph[4][0]; A[2][1] = ph[4][1]; A[2][2] = ph[0][0]; A[2][3] = ph[0][1];
        A[3][0] = ph[1][0]; A[3][1] = ph[1][1]; A[3][2] = ph[2][0]; A[3][3] = ph[2][1];
        A[4][0] = ph[3][0]; A[4][1] = ph[3][1]; A[4][2] = ph[4][0]; A[4][3] = ph[4][1];
        A[5][0] = pl[0][0]; A[5][1] = pl[0][1]; A[5][2] = pl[1][0]; A[5][3] = pl[1][1];
        A[6][0] = pl[2][0]; A[6][1] = pl[2][1]; A[6][2] = pl[3][0]; A[6][3] = pl[3][1];
        A[7][0] = pl[4][0]; A[7][1] = pl[4][1]; A[7][2] = q7r0;     A[7][3] = q7r1;

        // ===== z_{t+1} = A @ B  (80 mma, accumulate in place) =====
        #pragma unroll
        for (int j = 0; j < 10; j++) {
            z[j][0] = 0.0f; z[j][1] = 0.0f; z[j][2] = 0.0f; z[j][3] = 0.0f;
        }
        #pragma unroll
        for (int q = 0; q < 8; q++) {
            #pragma unroll
            for (int j = 0; j < 10; j++) {
                u64 b = sBfrag[(q * 10 + j) * 32 + lane];
                mma16816(z[j], A[q][0], A[q][1], A[q][2], A[q][3],
                         (u32)b, (u32)(b >> 32));
            }
        }
    }
}

extern "C" void kernel_launch(void* const* d_in, const int* in_sizes, int n_in,
                              void* d_out, int out_size) {
    const float* inp  = (const float*)d_in[0];
    const float* W1hh = (const float*)d_in[1];
    const float* b1hh = (const float*)d_in[2];
    const float* W2hh = (const float*)d_in[3];
    const float* b2hh = (const float*)d_in[4];
    const float* W1ho = (const float*)d_in[5];
    const float* b1ho = (const float*)d_in[6];
    const float* W2ho = (const float*)d_in[7];
    const float* b2ho = (const float*)d_in[8];
    float* out = (float*)d_out;

    dim3 grid(BATCH / EPB);   // 128 blocks x 256 threads (8 independent warps each)
    dim3 block(THREADS);
    rnn_mma_kernel<<<grid, block>>>(inp, W1hh, b1hh, W2hh, b2hh,
                                    W1ho, b1ho, W2ho, b2ho, out);
}